// round 4
// baseline (speedup 1.0000x reference)
#include <cuda_runtime.h>

#define THREADS 128   // 2 rows per CTA, 64 lanes (2 warps) per row

__device__ __forceinline__ void cmul_v(float& rr, float& ri,
                                       float ar, float ai, float br, float bi) {
    rr = fmaf(ar, br, -ai * bi);
    ri = fmaf(ar, bi,  ai * br);
}

// 16-point radix-2 DIF FFT in registers. Natural-order input,
// bit-reversed output: reg j holds X[br4(j)].
__device__ __forceinline__ void fft16(float* ar, float* ai)
{
    constexpr float TC[8] = { 1.0f, 0.92387953251128674f, 0.70710678118654752f,
                              0.38268343236508977f, 0.0f, -0.38268343236508977f,
                             -0.70710678118654752f, -0.92387953251128674f };
    constexpr float TS[8] = { 0.0f, -0.38268343236508977f, -0.70710678118654752f,
                             -0.92387953251128674f, -1.0f, -0.92387953251128674f,
                             -0.70710678118654752f, -0.38268343236508977f };
#pragma unroll
    for (int s = 0; s < 4; s++) {
        const int span = 8 >> s;
        const int tstep = 1 << s;
#pragma unroll
        for (int b = 0; b < 16; b += 2 * span) {
#pragma unroll
            for (int j = 0; j < span; j++) {
                const int i0 = b + j, i1 = b + j + span;
                float ur = ar[i0], ui = ai[i0];
                float vr = ar[i1], vi = ai[i1];
                ar[i0] = ur + vr;
                ai[i0] = ui + vi;
                float dr = ur - vr, di = ui - vi;
                const float wr = TC[j * tstep], wi = TS[j * tstep];
                ar[i1] = dr * wr - di * wi;
                ai[i1] = dr * wi + di * wr;
            }
        }
    }
}

// Combine two half-FFTs (even/odd split across lane pair l <-> l^16) into a
// 32-pt FFT via shfl. Lane h=0 holds E[K], h=1 holds O[K], K=br4(j).
// After: lane h holds X32[h*16 + br4(j)].
__device__ __forceinline__ void combine32(float* ar, float* ai, int h)
{
    constexpr float WC[16] = { 1.0f, 0.98078528040323044f, 0.92387953251128674f,
        0.83146961230254524f, 0.70710678118654752f, 0.55557023301960222f,
        0.38268343236508977f, 0.19509032201612827f, 0.0f, -0.19509032201612827f,
       -0.38268343236508977f, -0.55557023301960222f, -0.70710678118654752f,
       -0.83146961230254524f, -0.92387953251128674f, -0.98078528040323044f };
    constexpr float WS[16] = { 0.0f, -0.19509032201612827f, -0.38268343236508977f,
       -0.55557023301960222f, -0.70710678118654752f, -0.83146961230254524f,
       -0.92387953251128674f, -0.98078528040323044f, -1.0f, -0.98078528040323044f,
       -0.92387953251128674f, -0.83146961230254524f, -0.70710678118654752f,
       -0.55557023301960222f, -0.38268343236508977f, -0.19509032201612827f };

    const float sgn = h ? -1.0f : 1.0f;
#pragma unroll
    for (int j = 0; j < 16; j++) {
        const int K = ((j & 1) << 3) | ((j & 2) << 1) | ((j & 4) >> 1) | ((j & 8) >> 3);
        float br = __shfl_xor_sync(0xffffffffu, ar[j], 16);
        float bi = __shfl_xor_sync(0xffffffffu, ai[j], 16);
        float er = h ? br : ar[j];
        float ei = h ? bi : ai[j];
        float pr = h ? ar[j] : br;
        float pi = h ? ai[j] : bi;
        float tr, ti;
        cmul_v(tr, ti, pr, pi, WC[K], WS[K]);
        ar[j] = fmaf(sgn, tr, er);
        ai[j] = fmaf(sgn, ti, ei);
    }
}

// Four-step 1024 = 32 x 32. 64 lanes (2 warps) per row, 2 rows per CTA.
// Each 32-pt sub-FFT is done by a lane pair: fft16 per lane + shfl combine.
// Inter-phase twiddles generated by an incremental complex-multiply chain
// (2 sincos/thread instead of 16). float2 smem transpose, per-row barriers.
__global__ void __launch_bounds__(THREADS, 9) fft1024_kernel(
    const float* __restrict__ xin, float* __restrict__ xout)
{
    __shared__ float2 sz[2][32 * 33];

    const int tid = threadIdx.x;
    const int r = tid >> 6;          // row within CTA (0/1)
    const int w = (tid >> 5) & 1;    // warp-half of the row
    const int l = tid & 31;
    const int h = l >> 4;            // even/odd sample half
    const int q = l & 15;

    const int row = blockIdx.x * 2 + r;
    const float2* __restrict__ xb =
        reinterpret_cast<const float2*>(xin) + (size_t)row * 1024;
    float2* __restrict__ yb =
        reinterpret_cast<float2*>(xout) + (size_t)row * 1024;

    float ar[16], ai[16];
    const int n1 = w * 16 + q;

    // ================= Phase A: column FFTs over n2, column n1 =============
#pragma unroll
    for (int j = 0; j < 16; j++) {
        float2 v = __ldcs(&xb[(2 * j + h) * 32 + n1]);
        ar[j] = v.x;
        ai[j] = v.y;
    }
    fft16(ar, ai);
    combine32(ar, ai, h);   // lane holds Y[n1][k1], k1 = h*16 + br4(j)

    // inter-phase twiddle W1024^(n1*k1) by incremental chain over k1 = h*16+jj
    const float th = -6.2831853071795864769e0f / 1024.0f * (float)n1;
    float cs, ss;
    __sincosf(th, &ss, &cs);          // step = W1024^n1
    float wr, wi;
    if (h) {
        __sincosf(16.0f * th, &wi, &wr);  // start = W1024^(16*n1)
    } else {
        wr = 1.0f; wi = 0.0f;
    }
    float2* sp = &sz[r][h * 16 * 33 + n1];
#pragma unroll
    for (int jj = 0; jj < 16; jj++) {
        const int j = ((jj & 1) << 3) | ((jj & 2) << 1) |
                      ((jj & 4) >> 1) | ((jj & 8) >> 3);   // br4(jj)
        float tr, ti;
        cmul_v(tr, ti, ar[j], ai[j], wr, wi);
        sp[jj * 33] = make_float2(tr, ti);
        if (jj < 15) {
            float nwr;
            cmul_v(nwr, wi, wr, wi, cs, ss);
            wr = nwr;
        }
    }
    asm volatile("bar.sync %0, 64;" :: "r"(r + 1) : "memory");

    // ================= Phase B: row FFTs over n1, row k1 = n1-slot ==========
    const float2* lp = &sz[r][n1 * 33 + h];
#pragma unroll
    for (int j = 0; j < 16; j++) {
        float2 v = lp[2 * j];
        ar[j] = v.x;
        ai[j] = v.y;
    }
    fft16(ar, ai);
    combine32(ar, ai, h);   // lane holds X[n1 + 32*k2], k2 = h*16 + br4(j)

#pragma unroll
    for (int j = 0; j < 16; j++) {
        const int k2 = h * 16 +
            (((j & 1) << 3) | ((j & 2) << 1) | ((j & 4) >> 1) | ((j & 8) >> 3));
        __stcs(&yb[n1 + 32 * k2], make_float2(ar[j], ai[j]));
    }
}

extern "C" void kernel_launch(void* const* d_in, const int* in_sizes, int n_in,
                              void* d_out, int out_size)
{
    const float* x = (const float*)d_in[0];
    float* y = (float*)d_out;
    const int B = in_sizes[0] / 2048;   // 1024 complex per row
    fft1024_kernel<<<B / 2, THREADS>>>(x, y);
}

// round 5
// speedup vs baseline: 1.0583x; 1.0583x over previous
#include <cuda_runtime.h>

#define THREADS 128   // 2 rows per CTA, 64 lanes (2 warps) per row

__device__ __forceinline__ void cmul_v(float& rr, float& ri,
                                       float ar, float ai, float br, float bi) {
    rr = fmaf(ar, br, -ai * bi);
    ri = fmaf(ar, bi,  ai * br);
}

// 16-point radix-2 DIF FFT in registers. Natural-order input,
// bit-reversed output: reg j holds X[br4(j)]. Trivial twiddles constant-fold.
__device__ __forceinline__ void fft16(float* ar, float* ai)
{
    constexpr float TC[8] = { 1.0f, 0.92387953251128674f, 0.70710678118654752f,
                              0.38268343236508977f, 0.0f, -0.38268343236508977f,
                             -0.70710678118654752f, -0.92387953251128674f };
    constexpr float TS[8] = { 0.0f, -0.38268343236508977f, -0.70710678118654752f,
                             -0.92387953251128674f, -1.0f, -0.92387953251128674f,
                             -0.70710678118654752f, -0.38268343236508977f };
#pragma unroll
    for (int s = 0; s < 4; s++) {
        const int span = 8 >> s;
        const int tstep = 1 << s;
#pragma unroll
        for (int b = 0; b < 16; b += 2 * span) {
#pragma unroll
            for (int j = 0; j < span; j++) {
                const int i0 = b + j, i1 = b + j + span;
                float ur = ar[i0], ui = ai[i0];
                float vr = ar[i1], vi = ai[i1];
                ar[i0] = ur + vr;
                ai[i0] = ui + vi;
                float dr = ur - vr, di = ui - vi;
                const float wr = TC[j * tstep], wi = TS[j * tstep];
                ar[i1] = dr * wr - di * wi;
                ai[i1] = dr * wi + di * wr;
            }
        }
    }
}

// Combine two half-FFTs (even/odd split across lane pair l <-> l^16) into a
// 32-pt FFT. Lane h=0 holds E[K], h=1 holds O[K], K=br4(j).
// Select-free: h=1 lanes twiddle in place (W32^K * O), then both halves
// exchange and fold:  r = recv + sgn*own  (sgn = +1 for h=0, -1 for h=1).
//   h=0: E + (W*O)   h=1: E - (W*O)  -> lane h ends with X32[h*16 + K].
__device__ __forceinline__ void combine32(float* ar, float* ai, int h, float sgn)
{
    constexpr float WC[16] = { 1.0f, 0.98078528040323044f, 0.92387953251128674f,
        0.83146961230254524f, 0.70710678118654752f, 0.55557023301960222f,
        0.38268343236508977f, 0.19509032201612827f, 0.0f, -0.19509032201612827f,
       -0.38268343236508977f, -0.55557023301960222f, -0.70710678118654752f,
       -0.83146961230254524f, -0.92387953251128674f, -0.98078528040323044f };
    constexpr float WS[16] = { 0.0f, -0.19509032201612827f, -0.38268343236508977f,
       -0.55557023301960222f, -0.70710678118654752f, -0.83146961230254524f,
       -0.92387953251128674f, -0.98078528040323044f, -1.0f, -0.98078528040323044f,
       -0.92387953251128674f, -0.83146961230254524f, -0.70710678118654752f,
       -0.55557023301960222f, -0.38268343236508977f, -0.19509032201612827f };

    if (h) {
#pragma unroll
        for (int j = 0; j < 16; j++) {
            const int K = ((j & 1) << 3) | ((j & 2) << 1) |
                          ((j & 4) >> 1) | ((j & 8) >> 3);
            float tr, ti;
            cmul_v(tr, ti, ar[j], ai[j], WC[K], WS[K]);
            ar[j] = tr;
            ai[j] = ti;
        }
    }
#pragma unroll
    for (int j = 0; j < 16; j++) {
        float br = __shfl_xor_sync(0xffffffffu, ar[j], 16);
        float bi = __shfl_xor_sync(0xffffffffu, ai[j], 16);
        ar[j] = fmaf(sgn, ar[j], br);
        ai[j] = fmaf(sgn, ai[j], bi);
    }
}

// Four-step 1024 = 32 x 32. 64 lanes (2 warps) per row, 2 rows per CTA.
// Each 32-pt sub-FFT is a lane pair: fft16 per lane + one shfl combine stage.
// One float2 smem transpose between phases (conflict-free per half-warp).
__global__ void __launch_bounds__(THREADS, 8) fft1024_kernel(
    const float* __restrict__ xin, float* __restrict__ xout)
{
    __shared__ float2 sz[2][32 * 33];

    const int tid = threadIdx.x;
    const int r = tid >> 6;          // row within CTA (0/1)
    const int w = (tid >> 5) & 1;    // warp-half of the row
    const int l = tid & 31;
    const int h = l >> 4;            // even/odd sample half
    const int q = l & 15;
    const float sgn = h ? -1.0f : 1.0f;

    const int row = blockIdx.x * 2 + r;
    const float2* __restrict__ xb =
        reinterpret_cast<const float2*>(xin) + (size_t)row * 1024;
    float2* __restrict__ yb =
        reinterpret_cast<float2*>(xout) + (size_t)row * 1024;

    float ar[16], ai[16];
    const int n1 = w * 16 + q;

    // ================= Phase A: column FFTs over n2, column n1 =============
#pragma unroll
    for (int j = 0; j < 16; j++) {
        float2 v = __ldcs(&xb[(2 * j + h) * 32 + n1]);
        ar[j] = v.x;
        ai[j] = v.y;
    }
    fft16(ar, ai);
    combine32(ar, ai, h, sgn);   // lane holds Y[n1][k1], k1 = h*16 + br4(j)

    // inter-phase twiddle W1024^(n1*k1), store transposed smem[k1][n1]
    const float base = -6.2831853071795864769e0f / 1024.0f * (float)n1;
    float2* sp = &sz[r][h * 16 * 33 + n1];
#pragma unroll
    for (int j = 0; j < 16; j++) {
        const int K = ((j & 1) << 3) | ((j & 2) << 1) |
                      ((j & 4) >> 1) | ((j & 8) >> 3);          // br4(j)
        const int k1 = h * 16 + K;
        float s, c;
        __sincosf(base * (float)k1, &s, &c);
        float tr, ti;
        cmul_v(tr, ti, ar[j], ai[j], c, s);
        sp[K * 33] = make_float2(tr, ti);
    }
    __syncthreads();

    // ================= Phase B: row FFTs over n1, row k1 = n1-slot ==========
    const float2* lp = &sz[r][n1 * 33 + h];
#pragma unroll
    for (int j = 0; j < 16; j++) {
        float2 v = lp[2 * j];
        ar[j] = v.x;
        ai[j] = v.y;
    }
    fft16(ar, ai);
    combine32(ar, ai, h, sgn);   // lane holds X[n1 + 32*k2], k2 = h*16 + br4(j)

#pragma unroll
    for (int j = 0; j < 16; j++) {
        const int k2 = h * 16 +
            (((j & 1) << 3) | ((j & 2) << 1) | ((j & 4) >> 1) | ((j & 8) >> 3));
        __stcs(&yb[n1 + 32 * k2], make_float2(ar[j], ai[j]));
    }
}

extern "C" void kernel_launch(void* const* d_in, const int* in_sizes, int n_in,
                              void* d_out, int out_size)
{
    const float* x = (const float*)d_in[0];
    float* y = (float*)d_out;
    const int B = in_sizes[0] / 2048;   // 1024 complex per row
    fft1024_kernel<<<B / 2, THREADS>>>(x, y);
}

// round 6
// speedup vs baseline: 1.0597x; 1.0014x over previous
#include <cuda_runtime.h>

#define THREADS 128   // 2 rows per CTA, 64 lanes (2 warps) per row

// ===================== compile-time twiddle table =======================
// TW[k*32 + n] = exp(-2*pi*i * n*k / 1024), n,k in [0,32). Built at compile
// time via constexpr Taylor series (double precision, |x|<=pi, 13 terms).
__host__ __device__ constexpr double tsin_(double x) {
    double t = x, s = x;
    for (int k = 1; k < 13; k++) { t *= -x * x / ((2.0 * k) * (2.0 * k + 1.0)); s += t; }
    return s;
}
__host__ __device__ constexpr double tcos_(double x) {
    double t = 1.0, s = 1.0;
    for (int k = 1; k < 13; k++) { t *= -x * x / ((2.0 * k - 1.0) * (2.0 * k)); s += t; }
    return s;
}
struct alignas(16) TwTab { float2 v[1024]; };
__host__ __device__ constexpr TwTab make_tw_() {
    TwTab t{};
    constexpr double PI = 3.14159265358979323846;
    for (int k = 0; k < 32; k++)
        for (int n = 0; n < 32; n++) {
            int m = n * k;                  // < 1024
            double ang = -2.0 * PI * (double)m / 1024.0;
            if (ang < -PI) ang += 2.0 * PI; // reduce to [-pi, pi]
            t.v[k * 32 + n] = float2{ (float)tcos_(ang), (float)tsin_(ang) };
        }
    return t;
}
__device__ const TwTab TW = make_tw_();

__device__ __forceinline__ void cmul_v(float& rr, float& ri,
                                       float ar, float ai, float br, float bi) {
    rr = fmaf(ar, br, -ai * bi);
    ri = fmaf(ar, bi,  ai * br);
}

// 16-point radix-4 DIF FFT (2 stages). Natural-order input; output digit-
// reversed base 4: reg j=4m+t holds X[4t+m], i.e. X[dr4(j)].
__device__ __forceinline__ void fft16(float* ar, float* ai)
{
    constexpr float Cq = 0.92387953251128674f;   // cos(pi/8)
    constexpr float Sq = 0.38268343236508977f;   // sin(pi/8)
    constexpr float Rh = 0.70710678118654752f;
    // W16^{j}, W16^{2j}, W16^{3j} for j=0..3
    constexpr float AR[4] = {1.f,  Cq,  Rh,  Sq}, AI[4] = {0.f, -Sq, -Rh, -Cq};
    constexpr float BR[4] = {1.f,  Rh, 0.f, -Rh}, BI[4] = {0.f, -Rh, -1.f, -Rh};
    constexpr float CR[4] = {1.f,  Sq, -Rh, -Cq}, CI[4] = {0.f, -Cq, -Rh,  Sq};

#pragma unroll
    for (int j = 0; j < 4; j++) {
        float t0r = ar[j]   + ar[j+8],  t0i = ai[j]   + ai[j+8];
        float t1r = ar[j]   - ar[j+8],  t1i = ai[j]   - ai[j+8];
        float t2r = ar[j+4] + ar[j+12], t2i = ai[j+4] + ai[j+12];
        float t3r = ai[j+4] - ai[j+12], t3i = ar[j+12] - ar[j+4]; // -i*(a1-a3)
        ar[j] = t0r + t2r;  ai[j] = t0i + t2i;
        float u1r = t1r + t3r, u1i = t1i + t3i;
        float u2r = t0r - t2r, u2i = t0i - t2i;
        float u3r = t1r - t3r, u3i = t1i - t3i;
        ar[j+4]  = u1r*AR[j] - u1i*AI[j];  ai[j+4]  = u1r*AI[j] + u1i*AR[j];
        ar[j+8]  = u2r*BR[j] - u2i*BI[j];  ai[j+8]  = u2r*BI[j] + u2i*BR[j];
        ar[j+12] = u3r*CR[j] - u3i*CI[j];  ai[j+12] = u3r*CI[j] + u3i*CR[j];
    }
#pragma unroll
    for (int g = 0; g < 4; g++) {
        const int b = 4 * g;
        float t0r = ar[b]   + ar[b+2], t0i = ai[b]   + ai[b+2];
        float t1r = ar[b]   - ar[b+2], t1i = ai[b]   - ai[b+2];
        float t2r = ar[b+1] + ar[b+3], t2i = ai[b+1] + ai[b+3];
        float t3r = ai[b+1] - ai[b+3], t3i = ar[b+3] - ar[b+1];
        ar[b]   = t0r + t2r;  ai[b]   = t0i + t2i;
        ar[b+1] = t1r + t3r;  ai[b+1] = t1i + t3i;
        ar[b+2] = t0r - t2r;  ai[b+2] = t0i - t2i;
        ar[b+3] = t1r - t3r;  ai[b+3] = t1i - t3i;
    }
}

__device__ __forceinline__ int dr4(int j) { return ((j & 3) << 2) | (j >> 2); }

// Combine two half-FFTs (even/odd split across lane pair l <-> l^16) into a
// 32-pt FFT. Lane h=0 holds E[K], h=1 holds O[K], K=dr4(j). h=1 lanes twiddle
// in place (W32^K * O), then symmetric fold: r = recv + sgn*own.
__device__ __forceinline__ void combine32(float* ar, float* ai, int h, float sgn)
{
    constexpr float WC[16] = { 1.0f, 0.98078528040323044f, 0.92387953251128674f,
        0.83146961230254524f, 0.70710678118654752f, 0.55557023301960222f,
        0.38268343236508977f, 0.19509032201612827f, 0.0f, -0.19509032201612827f,
       -0.38268343236508977f, -0.55557023301960222f, -0.70710678118654752f,
       -0.83146961230254524f, -0.92387953251128674f, -0.98078528040323044f };
    constexpr float WS[16] = { 0.0f, -0.19509032201612827f, -0.38268343236508977f,
       -0.55557023301960222f, -0.70710678118654752f, -0.83146961230254524f,
       -0.92387953251128674f, -0.98078528040323044f, -1.0f, -0.98078528040323044f,
       -0.92387953251128674f, -0.83146961230254524f, -0.70710678118654752f,
       -0.55557023301960222f, -0.38268343236508977f, -0.19509032201612827f };

    if (h) {
#pragma unroll
        for (int j = 0; j < 16; j++) {
            const int K = dr4(j);
            float tr, ti;
            cmul_v(tr, ti, ar[j], ai[j], WC[K], WS[K]);
            ar[j] = tr;
            ai[j] = ti;
        }
    }
#pragma unroll
    for (int j = 0; j < 16; j++) {
        float br = __shfl_xor_sync(0xffffffffu, ar[j], 16);
        float bi = __shfl_xor_sync(0xffffffffu, ai[j], 16);
        ar[j] = fmaf(sgn, ar[j], br);
        ai[j] = fmaf(sgn, ai[j], bi);
    }
}

// Four-step 1024 = 32 x 32. 64 lanes (2 warps) per row, 2 rows per CTA.
// Each 32-pt sub-FFT is a lane pair: radix-4 fft16 per lane + one shfl
// combine stage. Inter-phase twiddles from compile-time table (no MUFU).
__global__ void __launch_bounds__(THREADS, 8) fft1024_kernel(
    const float* __restrict__ xin, float* __restrict__ xout)
{
    __shared__ float2 sz[2][32 * 33];

    const int tid = threadIdx.x;
    const int r = tid >> 6;          // row within CTA (0/1)
    const int w = (tid >> 5) & 1;    // warp-half of the row
    const int l = tid & 31;
    const int h = l >> 4;            // even/odd sample half
    const int q = l & 15;
    const float sgn = h ? -1.0f : 1.0f;

    const int row = blockIdx.x * 2 + r;
    const float2* __restrict__ xb =
        reinterpret_cast<const float2*>(xin) + (size_t)row * 1024;
    float2* __restrict__ yb =
        reinterpret_cast<float2*>(xout) + (size_t)row * 1024;

    float ar[16], ai[16];
    const int n1 = w * 16 + q;

    // ================= Phase A: column FFTs over n2, column n1 =============
#pragma unroll
    for (int j = 0; j < 16; j++) {
        float2 v = __ldcs(&xb[(2 * j + h) * 32 + n1]);
        ar[j] = v.x;
        ai[j] = v.y;
    }
    fft16(ar, ai);
    combine32(ar, ai, h, sgn);   // lane holds Y[n1][k1], k1 = h*16 + dr4(j)

    // inter-phase twiddle W1024^(n1*k1) from table, store transposed
    const float2* __restrict__ twp = TW.v + h * 512 + n1;  // + K*32
    float2* sp = &sz[r][h * 16 * 33 + n1];
#pragma unroll
    for (int j = 0; j < 16; j++) {
        const int K = dr4(j);
        const float2 wv = twp[K * 32];
        float tr, ti;
        cmul_v(tr, ti, ar[j], ai[j], wv.x, wv.y);
        sp[K * 33] = make_float2(tr, ti);
    }
    __syncthreads();

    // ================= Phase B: row FFTs over n1, row k1 = n1-slot ==========
    const float2* lp = &sz[r][n1 * 33 + h];
#pragma unroll
    for (int j = 0; j < 16; j++) {
        float2 v = lp[2 * j];
        ar[j] = v.x;
        ai[j] = v.y;
    }
    fft16(ar, ai);
    combine32(ar, ai, h, sgn);   // lane holds X[n1 + 32*k2], k2 = h*16 + dr4(j)

#pragma unroll
    for (int j = 0; j < 16; j++) {
        const int k2 = h * 16 + dr4(j);
        __stcs(&yb[n1 + 32 * k2], make_float2(ar[j], ai[j]));
    }
}

extern "C" void kernel_launch(void* const* d_in, const int* in_sizes, int n_in,
                              void* d_out, int out_size)
{
    const float* x = (const float*)d_in[0];
    float* y = (float*)d_out;
    const int B = in_sizes[0] / 2048;   // 1024 complex per row
    fft1024_kernel<<<B / 2, THREADS>>>(x, y);
}

// round 7
// speedup vs baseline: 1.0699x; 1.0096x over previous
#include <cuda_runtime.h>

#define THREADS 64   // one row (1024-pt FFT) per CTA: 2 warps, 32 lane-pairs

// ===================== compile-time twiddle table =======================
// TW[k*32 + n] = exp(-2*pi*i * n*k / 1024), n,k in [0,32).
__host__ __device__ constexpr double tsin_(double x) {
    double t = x, s = x;
    for (int k = 1; k < 13; k++) { t *= -x * x / ((2.0 * k) * (2.0 * k + 1.0)); s += t; }
    return s;
}
__host__ __device__ constexpr double tcos_(double x) {
    double t = 1.0, s = 1.0;
    for (int k = 1; k < 13; k++) { t *= -x * x / ((2.0 * k - 1.0) * (2.0 * k)); s += t; }
    return s;
}
struct alignas(16) TwTab { float2 v[1024]; };
__host__ __device__ constexpr TwTab make_tw_() {
    TwTab t{};
    constexpr double PI = 3.14159265358979323846;
    for (int k = 0; k < 32; k++)
        for (int n = 0; n < 32; n++) {
            double ang = -2.0 * PI * (double)(n * k) / 1024.0;
            if (ang < -PI) ang += 2.0 * PI;
            t.v[k * 32 + n] = float2{ (float)tcos_(ang), (float)tsin_(ang) };
        }
    return t;
}
__device__ const TwTab TW = make_tw_();

__device__ __forceinline__ void cmul_v(float& rr, float& ri,
                                       float ar, float ai, float br, float bi) {
    rr = fmaf(ar, br, -ai * bi);
    ri = fmaf(ar, bi,  ai * br);
}

// 16-point radix-4 DIF FFT (2 stages). Natural input; reg j holds X[dr4(j)],
// dr4(j) = ((j&3)<<2) | (j>>2).
__device__ __forceinline__ void fft16(float* ar, float* ai)
{
    constexpr float Cq = 0.92387953251128674f;
    constexpr float Sq = 0.38268343236508977f;
    constexpr float Rh = 0.70710678118654752f;
    constexpr float AR[4] = {1.f,  Cq,  Rh,  Sq}, AI[4] = {0.f, -Sq, -Rh, -Cq};
    constexpr float BR[4] = {1.f,  Rh, 0.f, -Rh}, BI[4] = {0.f, -Rh, -1.f, -Rh};
    constexpr float CR[4] = {1.f,  Sq, -Rh, -Cq}, CI[4] = {0.f, -Cq, -Rh,  Sq};

#pragma unroll
    for (int j = 0; j < 4; j++) {
        float t0r = ar[j]   + ar[j+8],  t0i = ai[j]   + ai[j+8];
        float t1r = ar[j]   - ar[j+8],  t1i = ai[j]   - ai[j+8];
        float t2r = ar[j+4] + ar[j+12], t2i = ai[j+4] + ai[j+12];
        float t3r = ai[j+4] - ai[j+12], t3i = ar[j+12] - ar[j+4];
        ar[j] = t0r + t2r;  ai[j] = t0i + t2i;
        float u1r = t1r + t3r, u1i = t1i + t3i;
        float u2r = t0r - t2r, u2i = t0i - t2i;
        float u3r = t1r - t3r, u3i = t1i - t3i;
        ar[j+4]  = u1r*AR[j] - u1i*AI[j];  ai[j+4]  = u1r*AI[j] + u1i*AR[j];
        ar[j+8]  = u2r*BR[j] - u2i*BI[j];  ai[j+8]  = u2r*BI[j] + u2i*BR[j];
        ar[j+12] = u3r*CR[j] - u3i*CI[j];  ai[j+12] = u3r*CI[j] + u3i*CR[j];
    }
#pragma unroll
    for (int g = 0; g < 4; g++) {
        const int b = 4 * g;
        float t0r = ar[b]   + ar[b+2], t0i = ai[b]   + ai[b+2];
        float t1r = ar[b]   - ar[b+2], t1i = ai[b]   - ai[b+2];
        float t2r = ar[b+1] + ar[b+3], t2i = ai[b+1] + ai[b+3];
        float t3r = ai[b+1] - ai[b+3], t3i = ar[b+3] - ar[b+1];
        ar[b]   = t0r + t2r;  ai[b]   = t0i + t2i;
        ar[b+1] = t1r + t3r;  ai[b+1] = t1i + t3i;
        ar[b+2] = t0r - t2r;  ai[b+2] = t0i - t2i;
        ar[b+3] = t1r - t3r;  ai[b+3] = t1i - t3i;
    }
}

__device__ __forceinline__ int dr4(int j) { return ((j & 3) << 2) | (j >> 2); }

// DIF lane-pair split, applied BEFORE fft16. Lane h=0 holds x[j] (j=0..15),
// lane h=1 holds x[j+16]. After:
//   h=0: u[j] = x[j] + x[j+16]            -> fft16(u) gives even outputs
//   h=1: v[j] = (x[j] - x[j+16])*W32^j    -> fft16(v) gives odd outputs
// Combined with fft16's dr4 order: lane h, reg j => X32[2*dr4(j) + h].
// W32^j are compile-time immediates (no table, no MUFU).
__device__ __forceinline__ void dif_split32(float* ar, float* ai, int h)
{
    constexpr float WC[16] = { 1.0f, 0.98078528040323044f, 0.92387953251128674f,
        0.83146961230254524f, 0.70710678118654752f, 0.55557023301960222f,
        0.38268343236508977f, 0.19509032201612827f, 0.0f, -0.19509032201612827f,
       -0.38268343236508977f, -0.55557023301960222f, -0.70710678118654752f,
       -0.83146961230254524f, -0.92387953251128674f, -0.98078528040323044f };
    constexpr float WS[16] = { 0.0f, -0.19509032201612827f, -0.38268343236508977f,
       -0.55557023301960222f, -0.70710678118654752f, -0.83146961230254524f,
       -0.92387953251128674f, -0.98078528040323044f, -1.0f, -0.98078528040323044f,
       -0.92387953251128674f, -0.83146961230254524f, -0.70710678118654752f,
       -0.55557023301960222f, -0.38268343236508977f, -0.19509032201612827f };

#pragma unroll
    for (int j = 0; j < 16; j++) {
        float br = __shfl_xor_sync(0xffffffffu, ar[j], 16);
        float bi = __shfl_xor_sync(0xffffffffu, ai[j], 16);
        if (h) {
            float dr = br - ar[j], di = bi - ai[j];
            ar[j] = dr * WC[j] - di * WS[j];
            ai[j] = dr * WS[j] + di * WC[j];
        } else {
            ar[j] += br;
            ai[j] += bi;
        }
    }
}

// Four-step 1024 = 32 x 32, one row per 64-thread CTA.
// Each 32-pt sub-FFT: DIF lane-pair split (shfl) + radix-4 fft16 in regs.
// Single transposed smem exchange, row stride 34 (conflict-free for the
// float4 phase-B loads and the scalar phase-A stores).
__global__ void __launch_bounds__(THREADS, 16) fft1024_kernel(
    const float* __restrict__ xin, float* __restrict__ xout)
{
    __shared__ __align__(16) float2 sz[32 * 34];

    const int tid = threadIdx.x;     // 0..63
    const int w = tid >> 5;          // warp
    const int l = tid & 31;
    const int h = l >> 4;            // lane-pair half
    const int q = l & 15;
    const int n1 = w * 16 + q;       // column (phase A) / row (phase B)

    const float2* __restrict__ xb =
        reinterpret_cast<const float2*>(xin) + (size_t)blockIdx.x * 1024;
    float2* __restrict__ yb =
        reinterpret_cast<float2*>(xout) + (size_t)blockIdx.x * 1024;

    float ar[16], ai[16];

    // ===== Phase A: 32-pt FFT over n2, column n1 ===========================
    // lane h loads samples n2 = h*16 + j  (2 x 128B coalesced per warp-load)
#pragma unroll
    for (int j = 0; j < 16; j++) {
        float2 v = __ldcs(&xb[(h * 16 + j) * 32 + n1]);
        ar[j] = v.x;
        ai[j] = v.y;
    }
    dif_split32(ar, ai, h);
    fft16(ar, ai);          // lane h, reg j -> Y[n1][k1], k1 = 2*dr4(j)+h

    // inter-phase twiddle W1024^(n1*k1) from table; transposed store
#pragma unroll
    for (int j = 0; j < 16; j++) {
        const int k1 = 2 * dr4(j) + h;
        const float2 wv = TW.v[k1 * 32 + n1];
        float tr, ti;
        cmul_v(tr, ti, ar[j], ai[j], wv.x, wv.y);
        sz[k1 * 34 + n1] = make_float2(tr, ti);
    }
    __syncthreads();

    // ===== Phase B: 32-pt FFT over k1 within row n1 ========================
    // lane h reads contiguous elements h*16..h*16+15 of row n1 -> 8 x LDS.128
    {
        const float4* lp4 = reinterpret_cast<const float4*>(&sz[n1 * 34 + h * 16]);
#pragma unroll
        for (int i = 0; i < 8; i++) {
            float4 v = lp4[i];
            ar[2 * i]     = v.x;  ai[2 * i]     = v.y;
            ar[2 * i + 1] = v.z;  ai[2 * i + 1] = v.w;
        }
    }
    dif_split32(ar, ai, h);
    fft16(ar, ai);          // lane h, reg j -> X[n1 + 32*k2], k2 = 2*dr4(j)+h

#pragma unroll
    for (int j = 0; j < 16; j++) {
        const int k2 = 2 * dr4(j) + h;
        __stcs(&yb[n1 + 32 * k2], make_float2(ar[j], ai[j]));
    }
}

extern "C" void kernel_launch(void* const* d_in, const int* in_sizes, int n_in,
                              void* d_out, int out_size)
{
    const float* x = (const float*)d_in[0];
    float* y = (float*)d_out;
    const int B = in_sizes[0] / 2048;   // 1024 complex per row
    fft1024_kernel<<<B, THREADS>>>(x, y);
}